// round 7
// baseline (speedup 1.0000x reference)
#include <cuda_runtime.h>
#include <cuda_bf16.h>
#include <cstdint>

// Problem constants
#define S_LEN 2048
#define B_SZ 4
#define HID 2048
#define T_TOK 8192
#define FF 1408
#define FF2 2816
#define NEXP 8
#define NROWS 16384

// ---------------- scratch (device globals) ----------------
__device__ int   d_counts[NEXP];
__device__ int   d_offsets[NEXP + 1];
__device__ int   d_cursor[NEXP];
__device__ int   d_ea[T_TOK];
__device__ int   d_eb[T_TOK];
__device__ float d_wa[T_TOK];
__device__ float d_wb[T_TOK];
__device__ int   d_row_token[NROWS];
__device__ int   d_token_pos[T_TOK * 2];
__device__ int   d_bad1;
__device__ int   d_bad2;

__device__ __nv_bfloat16 d_a_hi[(size_t)NROWS * HID];
__device__ __nv_bfloat16 d_a_lo[(size_t)NROWS * HID];
__device__ __nv_bfloat16 d_g_hi[(size_t)NROWS * FF];
__device__ __nv_bfloat16 d_g_lo[(size_t)NROWS * FF];
__device__ __nv_bfloat16 d_w1_hi[(size_t)NEXP * HID * FF2];
__device__ __nv_bfloat16 d_w1_lo[(size_t)NEXP * HID * FF2];
__device__ __nv_bfloat16 d_w2_hi[(size_t)NEXP * FF * HID];
__device__ __nv_bfloat16 d_w2_lo[(size_t)NEXP * FF * HID];
__device__ float d_h[(size_t)NROWS * FF2];
__device__ float d_g[(size_t)NROWS * FF];
__device__ float d_y[(size_t)NROWS * HID];

// ---------------- PTX helpers ----------------
__device__ __forceinline__ uint32_t smem_u32(const void* p) {
    uint32_t a;
    asm("{ .reg .u64 t; cvta.to.shared.u64 t, %1; cvt.u32.u64 %0, t; }" : "=r"(a) : "l"(p));
    return a;
}
__device__ __forceinline__ void ldsm_x4(uint32_t* r, uint32_t addr) {
    asm volatile("ldmatrix.sync.aligned.m8n8.x4.shared.b16 {%0,%1,%2,%3}, [%4];"
        : "=r"(r[0]), "=r"(r[1]), "=r"(r[2]), "=r"(r[3]) : "r"(addr));
}
__device__ __forceinline__ void ldsm_x4_t(uint32_t* r, uint32_t addr) {
    asm volatile("ldmatrix.sync.aligned.m8n8.x4.trans.shared.b16 {%0,%1,%2,%3}, [%4];"
        : "=r"(r[0]), "=r"(r[1]), "=r"(r[2]), "=r"(r[3]) : "r"(addr));
}
__device__ __forceinline__ void mma16816(float* c, const uint32_t* a, const uint32_t* b) {
    asm volatile(
        "mma.sync.aligned.m16n8k16.row.col.f32.bf16.bf16.f32 "
        "{%0,%1,%2,%3}, {%4,%5,%6,%7}, {%8,%9}, {%0,%1,%2,%3};"
        : "+f"(c[0]), "+f"(c[1]), "+f"(c[2]), "+f"(c[3])
        : "r"(a[0]), "r"(a[1]), "r"(a[2]), "r"(a[3]), "r"(b[0]), "r"(b[1]));
}

// ---------------- routing (proven in R1) ----------------
__global__ void zero_counts_kernel() {
    if (threadIdx.x < NEXP) d_counts[threadIdx.x] = 0;
    if (threadIdx.x == 0) { d_bad1 = 0; d_bad2 = 0; }
}

__global__ void gate_kernel(const float* __restrict__ x, const float* __restrict__ wg) {
    int t = blockIdx.x;
    const float* xr = x + ((size_t)(t % S_LEN) * B_SZ + (t / S_LEN)) * HID;
    float acc[NEXP];
#pragma unroll
    for (int e = 0; e < NEXP; e++) acc[e] = 0.f;
    for (int h = threadIdx.x; h < HID; h += 256) {
        float xv = xr[h];
#pragma unroll
        for (int e = 0; e < NEXP; e++) acc[e] += xv * wg[e * HID + h];
    }
#pragma unroll
    for (int e = 0; e < NEXP; e++)
        for (int off = 16; off; off >>= 1)
            acc[e] += __shfl_down_sync(0xffffffffu, acc[e], off);
    __shared__ float red[8][NEXP];
    int warp = threadIdx.x >> 5, lane = threadIdx.x & 31;
    if (lane == 0)
#pragma unroll
        for (int e = 0; e < NEXP; e++) red[warp][e] = acc[e];
    __syncthreads();
    if (threadIdx.x == 0) {
        float logits[NEXP];
#pragma unroll
        for (int e = 0; e < NEXP; e++) {
            float s = 0.f;
            for (int w = 0; w < 8; w++) s += red[w][e];
            logits[e] = s;
        }
        float m = logits[0];
#pragma unroll
        for (int e = 1; e < NEXP; e++) m = fmaxf(m, logits[e]);
        float sc[NEXP], Z = 0.f;
#pragma unroll
        for (int e = 0; e < NEXP; e++) { sc[e] = expf(logits[e] - m); Z += sc[e]; }
        float invZ = 1.f / Z;
#pragma unroll
        for (int e = 0; e < NEXP; e++) sc[e] *= invZ;
        int e0 = 0;
#pragma unroll
        for (int e = 1; e < NEXP; e++) if (sc[e] > sc[e0]) e0 = e;
        int e1 = (e0 == 0) ? 1 : 0;
#pragma unroll
        for (int e = 0; e < NEXP; e++) if (e != e0 && sc[e] > sc[e1]) e1 = e;
        float s0 = sc[e0], s1 = sc[e1];
        float inv = 1.f / (s0 + s1 + 1e-20f);
        d_ea[t] = e0; d_eb[t] = e1;
        d_wa[t] = s0 * inv; d_wb[t] = s1 * inv;
        atomicAdd(&d_counts[e0], 1);
        atomicAdd(&d_counts[e1], 1);
    }
}

__global__ void scan_kernel() {
    int o = 0;
    d_offsets[0] = 0;
#pragma unroll
    for (int e = 0; e < NEXP; e++) { o += d_counts[e]; d_offsets[e + 1] = o; }
#pragma unroll
    for (int e = 0; e < NEXP; e++) d_cursor[e] = d_offsets[e];
}

__global__ void assign_kernel() {
    int t = blockIdx.x * blockDim.x + threadIdx.x;
    if (t >= T_TOK) return;
    int p0 = atomicAdd(&d_cursor[d_ea[t]], 1);
    d_row_token[p0] = t;
    d_token_pos[2 * t] = p0;
    int p1 = atomicAdd(&d_cursor[d_eb[t]], 1);
    d_row_token[p1] = t;
    d_token_pos[2 * t + 1] = p1;
}

// ---------------- gather permuted X rows, split fp32 -> bf16 hi/lo ----------------
__global__ void gather_split_kernel(const float* __restrict__ x) {
    int r = blockIdx.x;
    int t = d_row_token[r];
    const float2* xr = (const float2*)(x + ((size_t)(t % S_LEN) * B_SZ + (t / S_LEN)) * HID);
    __nv_bfloat162* ah = (__nv_bfloat162*)(d_a_hi + (size_t)r * HID);
    __nv_bfloat162* al = (__nv_bfloat162*)(d_a_lo + (size_t)r * HID);
    for (int j = threadIdx.x; j < HID / 2; j += 256) {
        float2 v = xr[j];
        __nv_bfloat162 h2 = __floats2bfloat162_rn(v.x, v.y);
        float r0 = v.x - __low2float(h2);
        float r1 = v.y - __high2float(h2);
        ah[j] = h2;
        al[j] = __floats2bfloat162_rn(r0, r1);
    }
}

// ---------------- elementwise weight split ----------------
__global__ void split_w_kernel(const float* __restrict__ W,
                               __nv_bfloat16* __restrict__ Whi,
                               __nv_bfloat16* __restrict__ Wlo, int n4) {
    int i = blockIdx.x * blockDim.x + threadIdx.x;
    if (i >= n4) return;
    float4 v = ((const float4*)W)[i];
    __nv_bfloat162 h0 = __floats2bfloat162_rn(v.x, v.y);
    __nv_bfloat162 h1 = __floats2bfloat162_rn(v.z, v.w);
    __nv_bfloat162 l0 = __floats2bfloat162_rn(v.x - __low2float(h0), v.y - __high2float(h0));
    __nv_bfloat162 l1 = __floats2bfloat162_rn(v.z - __low2float(h1), v.w - __high2float(h1));
    ((__nv_bfloat162*)Whi)[2 * i] = h0;
    ((__nv_bfloat162*)Whi)[2 * i + 1] = h1;
    ((__nv_bfloat162*)Wlo)[2 * i] = l0;
    ((__nv_bfloat162*)Wlo)[2 * i + 1] = l1;
}

// ---------------- swiglu: d_h fp32 -> d_g fp32 + bf16 hi/lo ----------------
__global__ void swiglu_split_kernel() {
    int r = blockIdx.x;
    const float* hr = d_h + (size_t)r * FF2;
    float2* gf = (float2*)(d_g + (size_t)r * FF);
    __nv_bfloat162* gh = (__nv_bfloat162*)(d_g_hi + (size_t)r * FF);
    __nv_bfloat162* gl = (__nv_bfloat162*)(d_g_lo + (size_t)r * FF);
    for (int j = threadIdx.x; j < FF / 2; j += 256) {
        float2 a = ((const float2*)hr)[j];
        float2 b = ((const float2*)(hr + FF))[j];
        float y0 = (a.x / (1.f + expf(-a.x))) * b.x;
        float y1 = (a.y / (1.f + expf(-a.y))) * b.y;
        gf[j] = make_float2(y0, y1);
        __nv_bfloat162 h2 = __floats2bfloat162_rn(y0, y1);
        float r0 = y0 - __low2float(h2);
        float r1 = y1 - __high2float(h2);
        gh[j] = h2;
        gl[j] = __floats2bfloat162_rn(r0, r1);
    }
}

// ---------------- bf16x3 mma.sync grouped GEMM (as R6) ----------------
#define A_STRIDE_B 80
#define B_STRIDE_B 272
#define OFF_AH 0
#define OFF_AL 10240
#define OFF_BH 20480
#define OFF_BL 29184
#define MMA_SMEM 37888

template <int MODE>
__global__ void __launch_bounds__(256, 1)
mma_gemm_kernel() {
    constexpr int Kd = (MODE == 0) ? HID : FF;
    constexpr int Nd = (MODE == 0) ? FF2 : HID;
    constexpr int NC = Kd / 32;

    int e = blockIdx.z;
    int seg0 = d_offsets[e], seg1 = d_offsets[e + 1];
    int row0 = seg0 + blockIdx.x * 128;
    if (row0 >= seg1) return;
    int col0 = blockIdx.y * 128;

    __shared__ __align__(128) char smem[MMA_SMEM];
    uint32_t sb = smem_u32(smem);

    int tid = threadIdx.x;
    int wid = tid >> 5, lane = tid & 31;
    int wm = wid >> 2, wn = wid & 3;

    const __nv_bfloat16* Ah;
    const __nv_bfloat16* Al;
    const __nv_bfloat16* Wh;
    const __nv_bfloat16* Wl;
    if (MODE == 0) { Ah = d_a_hi; Al = d_a_lo; Wh = d_w1_hi; Wl = d_w1_lo; }
    else           { Ah = d_g_hi; Al = d_g_lo; Wh = d_w2_hi; Wl = d_w2_lo; }

    int a_row = tid >> 1, a_half = tid & 1;
    int gr = min(row0 + a_row, NROWS - 1);
    const uint4* aH_src = (const uint4*)(Ah + (size_t)gr * Kd + a_half * 16);
    const uint4* aL_src = (const uint4*)(Al + (size_t)gr * Kd + a_half * 16);
    char* a_dst = smem + a_row * A_STRIDE_B + a_half * 32;
    int b_row = tid >> 3, b_seg = tid & 7;
    size_t wbase = (size_t)e * Kd * Nd + (size_t)b_row * Nd + col0 + b_seg * 16;
    const uint4* bH_src = (const uint4*)(Wh + wbase);
    const uint4* bL_src = (const uint4*)(Wl + wbase);
    char* b_dst = smem + b_row * B_STRIDE_B + b_seg * 32;

    float acc[4][4][4];
#pragma unroll
    for (int i = 0; i < 4; i++)
#pragma unroll
        for (int j = 0; j < 4; j++)
#pragma unroll
            for (int q = 0; q < 4; q++) acc[i][j][q] = 0.f;

    int blk = lane >> 3, lr = lane & 7;
    int a_rin = (blk & 1) * 8 + lr;
    int a_kof = (blk >> 1) * 8;
    int b_kin = (blk & 1) * 8 + lr;
    int b_nof = (blk >> 1) * 8;

    uint4 rah[2], ral[2], rbh[2], rbl[2];
    {
        rah[0] = aH_src[0];  rah[1] = aH_src[1];
        ral[0] = aL_src[0];  ral[1] = aL_src[1];
        rbh[0] = bH_src[0];  rbh[1] = bH_src[1];
        rbl[0] = bL_src[0];  rbl[1] = bL_src[1];
    }

    for (int i = 0; i < NC; i++) {
        __syncthreads();
        *(uint4*)(a_dst + OFF_AH) = rah[0];
        *(uint4*)(a_dst + OFF_AH + 16) = rah[1];
        *(uint4*)(a_dst + OFF_AL) = ral[0];
        *(uint4*)(a_dst + OFF_AL + 16) = ral[1];
        *(uint4*)(b_dst + OFF_BH) = rbh[0];
        *(uint4*)(b_dst + OFF_BH + 16) = rbh[1];
        *(uint4*)(b_dst + OFF_BL) = rbl[0];
        *(uint4*)(b_dst + OFF_BL + 16) = rbl[1];
        __syncthreads();

        if (i + 1 < NC) {
            const int c = i + 1;
            rah[0] = aH_src[c * 4];     rah[1] = aH_src[c * 4 + 1];
            ral[0] = aL_src[c * 4];     ral[1] = aL_src[c * 4 + 1];
            size_t bo = (size_t)c * 32 * Nd / 8;
            rbh[0] = bH_src[bo];        rbh[1] = bH_src[bo + 1];
            rbl[0] = bL_src[bo];        rbl[1] = bL_src[bo + 1];
        }

#pragma unroll
        for (int s = 0; s < 2; s++) {
            uint32_t ah[4][4], al[4][4], bh[4][2], bl[4][2];
#pragma unroll
            for (int mt = 0; mt < 4; mt++) {
                uint32_t aaddr = sb + (uint32_t)((wm * 64 + mt * 16 + a_rin) * A_STRIDE_B
                               + (s * 16 + a_kof) * 2);
                ldsm_x4(ah[mt], aaddr + OFF_AH);
                ldsm_x4(al[mt], aaddr + OFF_AL);
            }
#pragma unroll
            for (int q = 0; q < 2; q++) {
                uint32_t baddr = sb + (uint32_t)((s * 16 + b_kin) * B_STRIDE_B
                               + (wn * 32 + q * 16 + b_nof) * 2);
                uint32_t rh[4], rl[4];
                ldsm_x4_t(rh, baddr + OFF_BH);
                ldsm_x4_t(rl, baddr + OFF_BL);
                bh[q * 2][0] = rh[0]; bh[q * 2][1] = rh[1];
                bh[q * 2 + 1][0] = rh[2]; bh[q * 2 + 1][1] = rh[3];
                bl[q * 2][0] = rl[0]; bl[q * 2][1] = rl[1];
                bl[q * 2 + 1][0] = rl[2]; bl[q * 2 + 1][1] = rl[3];
            }
#pragma unroll
            for (int mt = 0; mt < 4; mt++)
#pragma unroll
                for (int nt = 0; nt < 4; nt++) {
                    mma16816(acc[mt][nt], ah[mt], bh[nt]);
                    mma16816(acc[mt][nt], ah[mt], bl[nt]);
                    mma16816(acc[mt][nt], al[mt], bh[nt]);
                }
        }
    }

    float* C = (MODE == 0) ? d_h : d_y;
    int g = lane >> 2, t4 = lane & 3;
#pragma unroll
    for (int mt = 0; mt < 4; mt++) {
        int rbase = row0 + wm * 64 + mt * 16;
#pragma unroll
        for (int nt = 0; nt < 4; nt++) {
            int col = col0 + wn * 32 + nt * 8 + 2 * t4;
            if (rbase + g < seg1)
                *(float2*)&C[(size_t)(rbase + g) * Nd + col] =
                    make_float2(acc[mt][nt][0], acc[mt][nt][1]);
            if (rbase + 8 + g < seg1)
                *(float2*)&C[(size_t)(rbase + 8 + g) * Nd + col] =
                    make_float2(acc[mt][nt][2], acc[mt][nt][3]);
        }
    }
}

// ---------------- deterministic sampled check of mma output ----------------
template <int MODE>
__global__ void check_kernel(const float* __restrict__ x, const float* __restrict__ W) {
    constexpr int Kd = (MODE == 0) ? HID : FF;
    constexpr int Nd = (MODE == 0) ? FF2 : HID;
    int j = blockIdx.x;
    uint32_t h = (uint32_t)j * 2654435761u;
    int r = (int)((h >> 7) % NROWS);
    int n = (int)(((h ^ (h >> 16)) * 40503u) % (uint32_t)Nd);
    int e = 0;
#pragma unroll
    for (int q = 0; q < NEXP - 1; q++) if (r >= d_offsets[q + 1]) e = q + 1;

    const float* arow;
    if (MODE == 0) {
        int t = d_row_token[r];
        arow = x + ((size_t)(t % S_LEN) * B_SZ + (t / S_LEN)) * HID;
    } else {
        arow = d_g + (size_t)r * FF;
    }
    const float* wcol = W + (size_t)e * Kd * Nd + n;
    float p = 0.f;
    for (int k = threadIdx.x; k < Kd; k += 256)
        p += arow[k] * wcol[(size_t)k * Nd];
    for (int off = 16; off; off >>= 1) p += __shfl_down_sync(0xffffffffu, p, off);
    __shared__ float red[8];
    if ((threadIdx.x & 31) == 0) red[threadIdx.x >> 5] = p;
    __syncthreads();
    if (threadIdx.x == 0) {
        float ref = 0.f;
        for (int w = 0; w < 8; w++) ref += red[w];
        float got = (MODE == 0) ? d_h[(size_t)r * Nd + n] : d_y[(size_t)r * Nd + n];
        if (fabsf(got - ref) > 1e-2f * (fabsf(ref) + 1.f)) {
            if (MODE == 0) atomicExch(&d_bad1, 1);
            else           atomicExch(&d_bad2, 1);
        }
    }
}

// ---------------- proven R1 SIMT GEMM, gated as fallback ----------------
template <int MODE>
__global__ void __launch_bounds__(256, 2)
simt_gemm_kernel(const float* __restrict__ Xin, const float* __restrict__ Wbase) {
    if (((MODE == 0) ? d_bad1 : d_bad2) == 0) return;
    constexpr int Kd = (MODE == 0) ? HID : FF;
    constexpr int Nd = (MODE == 0) ? FF2 : HID;
    float* __restrict__ C = (MODE == 0) ? d_h : d_y;

    int e = blockIdx.z;
    int seg0 = d_offsets[e], seg1 = d_offsets[e + 1];
    int row0 = seg0 + blockIdx.x * 128;
    if (row0 >= seg1) return;
    int col0 = blockIdx.y * 128;

    const float* W = Wbase + (size_t)e * Kd * Nd + col0;

    __shared__ float As[8][128];
    __shared__ float Bs[8][128];

    int tid = threadIdx.x;
    int a_row = tid >> 1;
    int a_col = (tid & 1) * 4;
    int grow = row0 + a_row;
    bool a_valid = grow < seg1;
    const float* Arow;
    if (MODE == 0) {
        int t = a_valid ? d_row_token[grow] : 0;
        Arow = Xin + ((size_t)(t % S_LEN) * B_SZ + (t / S_LEN)) * HID;
    } else {
        Arow = d_g + (size_t)(a_valid ? grow : 0) * Kd;
    }
    int b_row = tid >> 5;
    int b_col = (tid & 31) * 4;
    const float* Wp = W + (size_t)b_row * Nd + b_col;

    float acc[8][8];
#pragma unroll
    for (int i = 0; i < 8; i++)
#pragma unroll
        for (int j = 0; j < 8; j++) acc[i][j] = 0.f;

    int ty = tid >> 4, tx = tid & 15;

    for (int k0 = 0; k0 < Kd; k0 += 8) {
        float4 av = a_valid ? *(const float4*)(Arow + k0 + a_col)
                            : make_float4(0.f, 0.f, 0.f, 0.f);
        As[a_col + 0][a_row] = av.x;
        As[a_col + 1][a_row] = av.y;
        As[a_col + 2][a_row] = av.z;
        As[a_col + 3][a_row] = av.w;
        *(float4*)&Bs[b_row][b_col] = *(const float4*)(Wp + (size_t)k0 * Nd);
        __syncthreads();
#pragma unroll
        for (int k = 0; k < 8; k++) {
            float a[8], b[8];
#pragma unroll
            for (int i = 0; i < 8; i++) a[i] = As[k][ty * 8 + i];
#pragma unroll
            for (int j = 0; j < 8; j++) b[j] = Bs[k][tx * 8 + j];
#pragma unroll
            for (int i = 0; i < 8; i++)
#pragma unroll
                for (int j = 0; j < 8; j++) acc[i][j] += a[i] * b[j];
        }
        __syncthreads();
    }

#pragma unroll
    for (int i = 0; i < 8; i++) {
        int gr2 = row0 + ty * 8 + i;
        if (gr2 < seg1) {
            float* cp = C + (size_t)gr2 * Nd + col0 + tx * 8;
            *(float4*)cp = make_float4(acc[i][0], acc[i][1], acc[i][2], acc[i][3]);
            *(float4*)(cp + 4) = make_float4(acc[i][4], acc[i][5], acc[i][6], acc[i][7]);
        }
    }
}

// ---------------- swiglu refresh for fallback path ----------------
// If gemm1 was corrected by the SIMT fallback, d_g_hi/lo must be re-derived.
__global__ void swiglu_refresh_kernel() {
    if (d_bad1 == 0) return;
    int r = blockIdx.x;
    const float* hr = d_h + (size_t)r * FF2;
    float2* gf = (float2*)(d_g + (size_t)r * FF);
    __nv_bfloat162* gh = (__nv_bfloat162*)(d_g_hi + (size_t)r * FF);
    __nv_bfloat162* gl = (__nv_bfloat162*)(d_g_lo + (size_t)r * FF);
    for (int j = threadIdx.x; j < FF / 2; j += 256) {
        float2 a = ((const float2*)hr)[j];
        float2 b = ((const float2*)(hr + FF))[j];
        float y0 = (a.x / (1.f + expf(-a.x))) * b.x;
        float y1 = (a.y / (1.f + expf(-a.y))) * b.y;
        gf[j] = make_float2(y0, y1);
        __nv_bfloat162 h2 = __floats2bfloat162_rn(y0, y1);
        float r0 = y0 - __low2float(h2);
        float r1 = y1 - __high2float(h2);
        gh[j] = h2;
        gl[j] = __floats2bfloat162_rn(r0, r1);
    }
}

// ---------------- combine ----------------
__global__ void combine_kernel(float* __restrict__ out) {
    int v = blockIdx.x * blockDim.x + threadIdx.x;
    const int total = T_TOK * (HID / 4);
    if (v >= total) return;
    int t = v / (HID / 4);
    int h4 = v % (HID / 4);
    int p0 = d_token_pos[2 * t], p1 = d_token_pos[2 * t + 1];
    float wa = d_wa[t], wb = d_wb[t];
    const float4 y0 = *(const float4*)&d_y[(size_t)p0 * HID + h4 * 4];
    const float4 y1 = *(const float4*)&d_y[(size_t)p1 * HID + h4 * 4];
    float4 o;
    o.x = wa * y0.x + wb * y1.x;
    o.y = wa * y0.y + wb * y1.y;
    o.z = wa * y0.z + wb * y1.z;
    o.w = wa * y0.w + wb * y1.w;
    int s = t % S_LEN, b = t / S_LEN;
    *(float4*)&out[((size_t)s * B_SZ + b) * HID + h4 * 4] = o;
}

// ---------------- launch ----------------
extern "C" void kernel_launch(void* const* d_in, const int* in_sizes, int n_in,
                              void* d_out, int out_size) {
    const float* x  = (const float*)d_in[0];
    const float* wg = (const float*)d_in[1];
    const float* w1 = (const float*)d_in[2];
    const float* w2 = (const float*)d_in[3];
    float* out = (float*)d_out;

    zero_counts_kernel<<<1, 32>>>();
    gate_kernel<<<T_TOK, 256>>>(x, wg);
    scan_kernel<<<1, 1>>>();
    assign_kernel<<<T_TOK / 256, 256>>>();
    gather_split_kernel<<<NROWS, 256>>>(x);

    int w1n4 = NEXP * HID * FF2 / 4;
    int w2n4 = NEXP * FF * HID / 4;
    split_w_kernel<<<(w1n4 + 255) / 256, 256>>>(w1, d_w1_hi, d_w1_lo, w1n4);
    split_w_kernel<<<(w2n4 + 255) / 256, 256>>>(w2, d_w2_hi, d_w2_lo, w2n4);

    // GEMM1: mma attempt -> sampled verify -> conditional SIMT fallback
    mma_gemm_kernel<0><<<dim3(128, FF2 / 128, NEXP), 256>>>();
    check_kernel<0><<<8192, 256>>>(x, w1);
    simt_gemm_kernel<0><<<dim3(128, FF2 / 128, NEXP), 256>>>(x, w1);

    // swiglu (always), then refresh hi/lo if fallback rewrote d_h
    swiglu_split_kernel<<<NROWS, 256>>>();
    swiglu_refresh_kernel<<<NROWS, 256>>>();

    // GEMM2: mma attempt -> sampled verify -> conditional SIMT fallback
    mma_gemm_kernel<1><<<dim3(128, HID / 128, NEXP), 256>>>();
    check_kernel<1><<<8192, 256>>>(x, w2);
    simt_gemm_kernel<1><<<dim3(128, HID / 128, NEXP), 256>>>(nullptr, w2);

    combine_kernel<<<(T_TOK * (HID / 4)) / 256, 256>>>(out);
}

// round 8
// speedup vs baseline: 1.0042x; 1.0042x over previous
#include <cuda_runtime.h>
#include <cuda_bf16.h>
#include <cstdint>

// Problem constants
#define S_LEN 2048
#define B_SZ 4
#define HID 2048
#define T_TOK 8192
#define FF 1408
#define FF2 2816
#define NEXP 8
#define NROWS 16384

// ---------------- scratch (device globals) ----------------
__device__ int   d_counts[NEXP];
__device__ int   d_offsets[NEXP + 1];
__device__ int   d_cursor[NEXP];
__device__ int   d_ea[T_TOK];
__device__ int   d_eb[T_TOK];
__device__ float d_wa[T_TOK];
__device__ float d_wb[T_TOK];
__device__ int   d_row_token[NROWS];
__device__ int   d_token_pos[T_TOK * 2];
__device__ int   d_bad1;
__device__ int   d_bad2;

__device__ __nv_bfloat16 d_a_hi[(size_t)NROWS * HID];
__device__ __nv_bfloat16 d_a_lo[(size_t)NROWS * HID];
__device__ __nv_bfloat16 d_g_hi[(size_t)NROWS * FF];
__device__ __nv_bfloat16 d_g_lo[(size_t)NROWS * FF];
__device__ __nv_bfloat16 d_w1_hi[(size_t)NEXP * HID * FF2];
__device__ __nv_bfloat16 d_w1_lo[(size_t)NEXP * HID * FF2];
__device__ __nv_bfloat16 d_w2_hi[(size_t)NEXP * FF * HID];
__device__ __nv_bfloat16 d_w2_lo[(size_t)NEXP * FF * HID];
__device__ float d_h[(size_t)NROWS * FF2];
__device__ float d_g[(size_t)NROWS * FF];
__device__ float d_y[(size_t)NROWS * HID];

// ---------------- PTX helpers ----------------
__device__ __forceinline__ uint32_t smem_u32(const void* p) {
    uint32_t a;
    asm("{ .reg .u64 t; cvta.to.shared.u64 t, %1; cvt.u32.u64 %0, t; }" : "=r"(a) : "l"(p));
    return a;
}
__device__ __forceinline__ uint32_t lds32(uint32_t a) {
    uint32_t v;
    asm volatile("ld.shared.b32 %0, [%1];" : "=r"(v) : "r"(a));
    return v;
}
__device__ __forceinline__ uint32_t lds16(uint32_t a) {
    uint32_t v;
    asm volatile("ld.shared.u16 %0, [%1];" : "=r"(v) : "r"(a));
    return v;
}
__device__ __forceinline__ void ldsm_x4(uint32_t* r, uint32_t addr) {
    asm volatile("ldmatrix.sync.aligned.m8n8.x4.shared.b16 {%0,%1,%2,%3}, [%4];"
        : "=r"(r[0]), "=r"(r[1]), "=r"(r[2]), "=r"(r[3]) : "r"(addr));
}
__device__ __forceinline__ void ldsm_x4_t(uint32_t* r, uint32_t addr) {
    asm volatile("ldmatrix.sync.aligned.m8n8.x4.trans.shared.b16 {%0,%1,%2,%3}, [%4];"
        : "=r"(r[0]), "=r"(r[1]), "=r"(r[2]), "=r"(r[3]) : "r"(addr));
}
__device__ __forceinline__ void mma16816(float* c, const uint32_t* a, const uint32_t* b) {
    asm volatile(
        "mma.sync.aligned.m16n8k16.row.col.f32.bf16.bf16.f32 "
        "{%0,%1,%2,%3}, {%4,%5,%6,%7}, {%8,%9}, {%0,%1,%2,%3};"
        : "+f"(c[0]), "+f"(c[1]), "+f"(c[2]), "+f"(c[3])
        : "r"(a[0]), "r"(a[1]), "r"(a[2]), "r"(a[3]), "r"(b[0]), "r"(b[1]));
}

// ---------------- routing ----------------
__global__ void zero_counts_kernel() {
    if (threadIdx.x < NEXP) d_counts[threadIdx.x] = 0;
    if (threadIdx.x == 0) { d_bad1 = 0; d_bad2 = 0; }
}

__global__ void gate_kernel(const float* __restrict__ x, const float* __restrict__ wg) {
    int t = blockIdx.x;
    const float* xr = x + ((size_t)(t % S_LEN) * B_SZ + (t / S_LEN)) * HID;
    float acc[NEXP];
#pragma unroll
    for (int e = 0; e < NEXP; e++) acc[e] = 0.f;
    for (int h = threadIdx.x; h < HID; h += 256) {
        float xv = xr[h];
#pragma unroll
        for (int e = 0; e < NEXP; e++) acc[e] += xv * wg[e * HID + h];
    }
#pragma unroll
    for (int e = 0; e < NEXP; e++)
        for (int off = 16; off; off >>= 1)
            acc[e] += __shfl_down_sync(0xffffffffu, acc[e], off);
    __shared__ float red[8][NEXP];
    int warp = threadIdx.x >> 5, lane = threadIdx.x & 31;
    if (lane == 0)
#pragma unroll
        for (int e = 0; e < NEXP; e++) red[warp][e] = acc[e];
    __syncthreads();
    if (threadIdx.x == 0) {
        float logits[NEXP];
#pragma unroll
        for (int e = 0; e < NEXP; e++) {
            float s = 0.f;
            for (int w = 0; w < 8; w++) s += red[w][e];
            logits[e] = s;
        }
        float m = logits[0];
#pragma unroll
        for (int e = 1; e < NEXP; e++) m = fmaxf(m, logits[e]);
        float sc[NEXP], Z = 0.f;
#pragma unroll
        for (int e = 0; e < NEXP; e++) { sc[e] = expf(logits[e] - m); Z += sc[e]; }
        float invZ = 1.f / Z;
#pragma unroll
        for (int e = 0; e < NEXP; e++) sc[e] *= invZ;
        int e0 = 0;
#pragma unroll
        for (int e = 1; e < NEXP; e++) if (sc[e] > sc[e0]) e0 = e;
        int e1 = (e0 == 0) ? 1 : 0;
#pragma unroll
        for (int e = 0; e < NEXP; e++) if (e != e0 && sc[e] > sc[e1]) e1 = e;
        float s0 = sc[e0], s1 = sc[e1];
        float inv = 1.f / (s0 + s1 + 1e-20f);
        d_ea[t] = e0; d_eb[t] = e1;
        d_wa[t] = s0 * inv; d_wb[t] = s1 * inv;
        atomicAdd(&d_counts[e0], 1);
        atomicAdd(&d_counts[e1], 1);
    }
}

__global__ void scan_kernel() {
    int o = 0;
    d_offsets[0] = 0;
#pragma unroll
    for (int e = 0; e < NEXP; e++) { o += d_counts[e]; d_offsets[e + 1] = o; }
#pragma unroll
    for (int e = 0; e < NEXP; e++) d_cursor[e] = d_offsets[e];
}

__global__ void assign_kernel() {
    int t = blockIdx.x * blockDim.x + threadIdx.x;
    if (t >= T_TOK) return;
    int p0 = atomicAdd(&d_cursor[d_ea[t]], 1);
    d_row_token[p0] = t;
    d_token_pos[2 * t] = p0;
    int p1 = atomicAdd(&d_cursor[d_eb[t]], 1);
    d_row_token[p1] = t;
    d_token_pos[2 * t + 1] = p1;
}

// ---------------- gather permuted X rows, split fp32 -> bf16 hi/lo ----------------
__global__ void gather_split_kernel(const float* __restrict__ x) {
    int r = blockIdx.x;
    int t = d_row_token[r];
    const float2* xr = (const float2*)(x + ((size_t)(t % S_LEN) * B_SZ + (t / S_LEN)) * HID);
    __nv_bfloat162* ah = (__nv_bfloat162*)(d_a_hi + (size_t)r * HID);
    __nv_bfloat162* al = (__nv_bfloat162*)(d_a_lo + (size_t)r * HID);
    for (int j = threadIdx.x; j < HID / 2; j += 256) {
        float2 v = xr[j];
        __nv_bfloat162 h2 = __floats2bfloat162_rn(v.x, v.y);
        float r0 = v.x - __low2float(h2);
        float r1 = v.y - __high2float(h2);
        ah[j] = h2;
        al[j] = __floats2bfloat162_rn(r0, r1);
    }
}

// ---------------- elementwise weight split ----------------
__global__ void split_w_kernel(const float* __restrict__ W,
                               __nv_bfloat16* __restrict__ Whi,
                               __nv_bfloat16* __restrict__ Wlo, int n4) {
    int i = blockIdx.x * blockDim.x + threadIdx.x;
    if (i >= n4) return;
    float4 v = ((const float4*)W)[i];
    __nv_bfloat162 h0 = __floats2bfloat162_rn(v.x, v.y);
    __nv_bfloat162 h1 = __floats2bfloat162_rn(v.z, v.w);
    __nv_bfloat162 l0 = __floats2bfloat162_rn(v.x - __low2float(h0), v.y - __high2float(h0));
    __nv_bfloat162 l1 = __floats2bfloat162_rn(v.z - __low2float(h1), v.w - __high2float(h1));
    ((__nv_bfloat162*)Whi)[2 * i] = h0;
    ((__nv_bfloat162*)Whi)[2 * i + 1] = h1;
    ((__nv_bfloat162*)Wlo)[2 * i] = l0;
    ((__nv_bfloat162*)Wlo)[2 * i + 1] = l1;
}

// ---------------- swiglu: d_h fp32 -> d_g fp32 + bf16 hi/lo ----------------
__global__ void swiglu_split_kernel() {
    int r = blockIdx.x;
    const float* hr = d_h + (size_t)r * FF2;
    float2* gf = (float2*)(d_g + (size_t)r * FF);
    __nv_bfloat162* gh = (__nv_bfloat162*)(d_g_hi + (size_t)r * FF);
    __nv_bfloat162* gl = (__nv_bfloat162*)(d_g_lo + (size_t)r * FF);
    for (int j = threadIdx.x; j < FF / 2; j += 256) {
        float2 a = ((const float2*)hr)[j];
        float2 b = ((const float2*)(hr + FF))[j];
        float y0 = (a.x / (1.f + expf(-a.x))) * b.x;
        float y1 = (a.y / (1.f + expf(-a.y))) * b.y;
        gf[j] = make_float2(y0, y1);
        __nv_bfloat162 h2 = __floats2bfloat162_rn(y0, y1);
        float r0 = y0 - __low2float(h2);
        float r1 = y1 - __high2float(h2);
        gh[j] = h2;
        gl[j] = __floats2bfloat162_rn(r0, r1);
    }
}

// ---------------- bf16x3 mma.sync grouped GEMM ----------------
// LDSM=1: ldmatrix fragment loads (control). LDSM=0: manual LDS per PTX tables.
#define A_STRIDE_B 80
#define B_STRIDE_B 272
#define OFF_AH 0
#define OFF_AL 10240
#define OFF_BH 20480
#define OFF_BL 29184
#define MMA_SMEM 37888

template <int MODE, int LDSM>
__global__ void __launch_bounds__(256, 1)
mma_gemm_kernel() {
    constexpr int Kd = (MODE == 0) ? HID : FF;
    constexpr int Nd = (MODE == 0) ? FF2 : HID;
    constexpr int NC = Kd / 32;

    int e = blockIdx.z;
    int seg0 = d_offsets[e], seg1 = d_offsets[e + 1];
    int row0 = seg0 + blockIdx.x * 128;
    if (row0 >= seg1) return;
    int col0 = blockIdx.y * 128;

    __shared__ __align__(128) char smem[MMA_SMEM];
    uint32_t sb = smem_u32(smem);

    int tid = threadIdx.x;
    int wid = tid >> 5, lane = tid & 31;
    int wm = wid >> 2, wn = wid & 3;

    const __nv_bfloat16* Ah;
    const __nv_bfloat16* Al;
    const __nv_bfloat16* Wh;
    const __nv_bfloat16* Wl;
    if (MODE == 0) { Ah = d_a_hi; Al = d_a_lo; Wh = d_w1_hi; Wl = d_w1_lo; }
    else           { Ah = d_g_hi; Al = d_g_lo; Wh = d_w2_hi; Wl = d_w2_lo; }

    int a_row = tid >> 1, a_half = tid & 1;
    int gr = min(row0 + a_row, NROWS - 1);
    const uint4* aH_src = (const uint4*)(Ah + (size_t)gr * Kd + a_half * 16);
    const uint4* aL_src = (const uint4*)(Al + (size_t)gr * Kd + a_half * 16);
    char* a_dst = smem + a_row * A_STRIDE_B + a_half * 32;
    int b_row = tid >> 3, b_seg = tid & 7;
    size_t wbase = (size_t)e * Kd * Nd + (size_t)b_row * Nd + col0 + b_seg * 16;
    const uint4* bH_src = (const uint4*)(Wh + wbase);
    const uint4* bL_src = (const uint4*)(Wl + wbase);
    char* b_dst = smem + b_row * B_STRIDE_B + b_seg * 32;

    float acc[4][4][4];
#pragma unroll
    for (int i = 0; i < 4; i++)
#pragma unroll
        for (int j = 0; j < 4; j++)
#pragma unroll
            for (int q = 0; q < 4; q++) acc[i][j][q] = 0.f;

    int blk = lane >> 3, lr = lane & 7;
    int a_rin = (blk & 1) * 8 + lr;
    int a_kof = (blk >> 1) * 8;
    int b_kin = (blk & 1) * 8 + lr;
    int b_nof = (blk >> 1) * 8;
    int fr = lane >> 2, fcp = (lane & 3) * 2;   // manual fragment row / k-col pair

    uint4 rah[2], ral[2], rbh[2], rbl[2];
    {
        rah[0] = aH_src[0];  rah[1] = aH_src[1];
        ral[0] = aL_src[0];  ral[1] = aL_src[1];
        rbh[0] = bH_src[0];  rbh[1] = bH_src[1];
        rbl[0] = bL_src[0];  rbl[1] = bL_src[1];
    }

    for (int i = 0; i < NC; i++) {
        __syncthreads();
        *(uint4*)(a_dst + OFF_AH) = rah[0];
        *(uint4*)(a_dst + OFF_AH + 16) = rah[1];
        *(uint4*)(a_dst + OFF_AL) = ral[0];
        *(uint4*)(a_dst + OFF_AL + 16) = ral[1];
        *(uint4*)(b_dst + OFF_BH) = rbh[0];
        *(uint4*)(b_dst + OFF_BH + 16) = rbh[1];
        *(uint4*)(b_dst + OFF_BL) = rbl[0];
        *(uint4*)(b_dst + OFF_BL + 16) = rbl[1];
        __syncthreads();

        if (i + 1 < NC) {
            const int c = i + 1;
            rah[0] = aH_src[c * 4];     rah[1] = aH_src[c * 4 + 1];
            ral[0] = aL_src[c * 4];     ral[1] = aL_src[c * 4 + 1];
            size_t bo = (size_t)c * 32 * Nd / 8;
            rbh[0] = bH_src[bo];        rbh[1] = bH_src[bo + 1];
            rbl[0] = bL_src[bo];        rbl[1] = bL_src[bo + 1];
        }

#pragma unroll
        for (int s = 0; s < 2; s++) {
            uint32_t ah[4][4], al[4][4], bh[4][2], bl[4][2];
            if (LDSM) {
#pragma unroll
                for (int mt = 0; mt < 4; mt++) {
                    uint32_t aaddr = sb + (uint32_t)((wm * 64 + mt * 16 + a_rin) * A_STRIDE_B
                                   + (s * 16 + a_kof) * 2);
                    ldsm_x4(ah[mt], aaddr + OFF_AH);
                    ldsm_x4(al[mt], aaddr + OFF_AL);
                }
#pragma unroll
                for (int q = 0; q < 2; q++) {
                    uint32_t baddr = sb + (uint32_t)((s * 16 + b_kin) * B_STRIDE_B
                                   + (wn * 32 + q * 16 + b_nof) * 2);
                    uint32_t rh[4], rl[4];
                    ldsm_x4_t(rh, baddr + OFF_BH);
                    ldsm_x4_t(rl, baddr + OFF_BL);
                    bh[q * 2][0] = rh[0]; bh[q * 2][1] = rh[1];
                    bh[q * 2 + 1][0] = rh[2]; bh[q * 2 + 1][1] = rh[3];
                    bl[q * 2][0] = rl[0]; bl[q * 2][1] = rl[1];
                    bl[q * 2 + 1][0] = rl[2]; bl[q * 2 + 1][1] = rl[3];
                }
            } else {
                // Manual fragment loads per PTX mma tables (no ldmatrix).
#pragma unroll
                for (int mt = 0; mt < 4; mt++) {
                    uint32_t base = sb + (uint32_t)((wm * 64 + mt * 16 + fr) * A_STRIDE_B
                                  + (s * 16 + fcp) * 2);
                    ah[mt][0] = lds32(base + OFF_AH);
                    ah[mt][1] = lds32(base + OFF_AH + 8 * A_STRIDE_B);
                    ah[mt][2] = lds32(base + OFF_AH + 16);
                    ah[mt][3] = lds32(base + OFF_AH + 8 * A_STRIDE_B + 16);
                    al[mt][0] = lds32(base + OFF_AL);
                    al[mt][1] = lds32(base + OFF_AL + 8 * A_STRIDE_B);
                    al[mt][2] = lds32(base + OFF_AL + 16);
                    al[mt][3] = lds32(base + OFF_AL + 8 * A_STRIDE_B + 16);
                }
#pragma unroll
                for (int nt = 0; nt < 4; nt++) {
                    uint32_t nb = sb + (uint32_t)((s * 16 + fcp) * B_STRIDE_B
                                + (wn * 32 + nt * 8 + fr) * 2);
                    bh[nt][0] = lds16(nb + OFF_BH)
                              | (lds16(nb + OFF_BH + B_STRIDE_B) << 16);
                    bh[nt][1] = lds16(nb + OFF_BH + 8 * B_STRIDE_B)
                              | (lds16(nb + OFF_BH + 9 * B_STRIDE_B) << 16);
                    bl[nt][0] = lds16(nb + OFF_BL)
                              | (lds16(nb + OFF_BL + B_STRIDE_B) << 16);
                    bl[nt][1] = lds16(nb + OFF_BL + 8 * B_STRIDE_B)
                              | (lds16(nb + OFF_BL + 9 * B_STRIDE_B) << 16);
                }
            }
#pragma unroll
            for (int mt = 0; mt < 4; mt++)
#pragma unroll
                for (int nt = 0; nt < 4; nt++) {
                    mma16816(acc[mt][nt], ah[mt], bh[nt]);
                    mma16816(acc[mt][nt], ah[mt], bl[nt]);
                    mma16816(acc[mt][nt], al[mt], bh[nt]);
                }
        }
    }

    float* C = (MODE == 0) ? d_h : d_y;
    int g = lane >> 2, t4 = lane & 3;
#pragma unroll
    for (int mt = 0; mt < 4; mt++) {
        int rbase = row0 + wm * 64 + mt * 16;
#pragma unroll
        for (int nt = 0; nt < 4; nt++) {
            int col = col0 + wn * 32 + nt * 8 + 2 * t4;
            if (rbase + g < seg1)
                *(float2*)&C[(size_t)(rbase + g) * Nd + col] =
                    make_float2(acc[mt][nt][0], acc[mt][nt][1]);
            if (rbase + 8 + g < seg1)
                *(float2*)&C[(size_t)(rbase + 8 + g) * Nd + col] =
                    make_float2(acc[mt][nt][2], acc[mt][nt][3]);
        }
    }
}

// ---------------- deterministic sampled check of mma output ----------------
template <int MODE>
__global__ void check_kernel(const float* __restrict__ x, const float* __restrict__ W) {
    constexpr int Kd = (MODE == 0) ? HID : FF;
    constexpr int Nd = (MODE == 0) ? FF2 : HID;
    int j = blockIdx.x;
    uint32_t h = (uint32_t)j * 2654435761u;
    int r = (int)((h >> 7) % NROWS);
    int n = (int)(((h ^ (h >> 16)) * 40503u) % (uint32_t)Nd);
    int e = 0;
#pragma unroll
    for (int q = 0; q < NEXP - 1; q++) if (r >= d_offsets[q + 1]) e = q + 1;

    const float* arow;
    if (MODE == 0) {
        int t = d_row_token[r];
        arow = x + ((size_t)(t % S_LEN) * B_SZ + (t / S_LEN)) * HID;
    } else {
        arow = d_g + (size_t)r * FF;
    }
    const float* wcol = W + (size_t)e * Kd * Nd + n;
    float p = 0.f;
    for (int k = threadIdx.x; k < Kd; k += 256)
        p += arow[k] * wcol[(size_t)k * Nd];
    for (int off = 16; off; off >>= 1) p += __shfl_down_sync(0xffffffffu, p, off);
    __shared__ float red[8];
    if ((threadIdx.x & 31) == 0) red[threadIdx.x >> 5] = p;
    __syncthreads();
    if (threadIdx.x == 0) {
        float ref = 0.f;
        for (int w = 0; w < 8; w++) ref += red[w];
        float got = (MODE == 0) ? d_h[(size_t)r * Nd + n] : d_y[(size_t)r * Nd + n];
        if (fabsf(got - ref) > 1e-2f * (fabsf(ref) + 1.f)) {
            if (MODE == 0) atomicExch(&d_bad1, 1);
            else           atomicExch(&d_bad2, 1);
        }
    }
}

// ---------------- proven R1 SIMT GEMM, gated as fallback ----------------
template <int MODE>
__global__ void __launch_bounds__(256, 2)
simt_gemm_kernel(const float* __restrict__ Xin, const float* __restrict__ Wbase) {
    if (((MODE == 0) ? d_bad1 : d_bad2) == 0) return;
    constexpr int Kd = (MODE == 0) ? HID : FF;
    constexpr int Nd = (MODE == 0) ? FF2 : HID;
    float* __restrict__ C = (MODE == 0) ? d_h : d_y;

    int e = blockIdx.z;
    int seg0 = d_offsets[e], seg1 = d_offsets[e + 1];
    int row0 = seg0 + blockIdx.x * 128;
    if (row0 >= seg1) return;
    int col0 = blockIdx.y * 128;

    const float* W = Wbase + (size_t)e * Kd * Nd + col0;

    __shared__ float As[8][128];
    __shared__ float Bs[8][128];

    int tid = threadIdx.x;
    int a_row = tid >> 1;
    int a_col = (tid & 1) * 4;
    int grow = row0 + a_row;
    bool a_valid = grow < seg1;
    const float* Arow;
    if (MODE == 0) {
        int t = a_valid ? d_row_token[grow] : 0;
        Arow = Xin + ((size_t)(t % S_LEN) * B_SZ + (t / S_LEN)) * HID;
    } else {
        Arow = d_g + (size_t)(a_valid ? grow : 0) * Kd;
    }
    int b_row = tid >> 5;
    int b_col = (tid & 31) * 4;
    const float* Wp = W + (size_t)b_row * Nd + b_col;

    float acc[8][8];
#pragma unroll
    for (int i = 0; i < 8; i++)
#pragma unroll
        for (int j = 0; j < 8; j++) acc[i][j] = 0.f;

    int ty = tid >> 4, tx = tid & 15;

    for (int k0 = 0; k0 < Kd; k0 += 8) {
        float4 av = a_valid ? *(const float4*)(Arow + k0 + a_col)
                            : make_float4(0.f, 0.f, 0.f, 0.f);
        As[a_col + 0][a_row] = av.x;
        As[a_col + 1][a_row] = av.y;
        As[a_col + 2][a_row] = av.z;
        As[a_col + 3][a_row] = av.w;
        *(float4*)&Bs[b_row][b_col] = *(const float4*)(Wp + (size_t)k0 * Nd);
        __syncthreads();
#pragma unroll
        for (int k = 0; k < 8; k++) {
            float a[8], b[8];
#pragma unroll
            for (int i = 0; i < 8; i++) a[i] = As[k][ty * 8 + i];
#pragma unroll
            for (int j = 0; j < 8; j++) b[j] = Bs[k][tx * 8 + j];
#pragma unroll
            for (int i = 0; i < 8; i++)
#pragma unroll
                for (int j = 0; j < 8; j++) acc[i][j] += a[i] * b[j];
        }
        __syncthreads();
    }

#pragma unroll
    for (int i = 0; i < 8; i++) {
        int gr2 = row0 + ty * 8 + i;
        if (gr2 < seg1) {
            float* cp = C + (size_t)gr2 * Nd + col0 + tx * 8;
            *(float4*)cp = make_float4(acc[i][0], acc[i][1], acc[i][2], acc[i][3]);
            *(float4*)(cp + 4) = make_float4(acc[i][4], acc[i][5], acc[i][6], acc[i][7]);
        }
    }
}

// ---------------- swiglu refresh for fallback path ----------------
__global__ void swiglu_refresh_kernel() {
    if (d_bad1 == 0) return;
    int r = blockIdx.x;
    const float* hr = d_h + (size_t)r * FF2;
    float2* gf = (float2*)(d_g + (size_t)r * FF);
    __nv_bfloat162* gh = (__nv_bfloat162*)(d_g_hi + (size_t)r * FF);
    __nv_bfloat162* gl = (__nv_bfloat162*)(d_g_lo + (size_t)r * FF);
    for (int j = threadIdx.x; j < FF / 2; j += 256) {
        float2 a = ((const float2*)hr)[j];
        float2 b = ((const float2*)(hr + FF))[j];
        float y0 = (a.x / (1.f + expf(-a.x))) * b.x;
        float y1 = (a.y / (1.f + expf(-a.y))) * b.y;
        gf[j] = make_float2(y0, y1);
        __nv_bfloat162 h2 = __floats2bfloat162_rn(y0, y1);
        float r0 = y0 - __low2float(h2);
        float r1 = y1 - __high2float(h2);
        gh[j] = h2;
        gl[j] = __floats2bfloat162_rn(r0, r1);
    }
}

// ---------------- combine ----------------
__global__ void combine_kernel(float* __restrict__ out) {
    int v = blockIdx.x * blockDim.x + threadIdx.x;
    const int total = T_TOK * (HID / 4);
    if (v >= total) return;
    int t = v / (HID / 4);
    int h4 = v % (HID / 4);
    int p0 = d_token_pos[2 * t], p1 = d_token_pos[2 * t + 1];
    float wa = d_wa[t], wb = d_wb[t];
    const float4 y0 = *(const float4*)&d_y[(size_t)p0 * HID + h4 * 4];
    const float4 y1 = *(const float4*)&d_y[(size_t)p1 * HID + h4 * 4];
    float4 o;
    o.x = wa * y0.x + wb * y1.x;
    o.y = wa * y0.y + wb * y1.y;
    o.z = wa * y0.z + wb * y1.z;
    o.w = wa * y0.w + wb * y1.w;
    int s = t % S_LEN, b = t / S_LEN;
    *(float4*)&out[((size_t)s * B_SZ + b) * HID + h4 * 4] = o;
}

// ---------------- launch ----------------
extern "C" void kernel_launch(void* const* d_in, const int* in_sizes, int n_in,
                              void* d_out, int out_size) {
    const float* x  = (const float*)d_in[0];
    const float* wg = (const float*)d_in[1];
    const float* w1 = (const float*)d_in[2];
    const float* w2 = (const float*)d_in[3];
    float* out = (float*)d_out;

    zero_counts_kernel<<<1, 32>>>();
    gate_kernel<<<T_TOK, 256>>>(x, wg);
    scan_kernel<<<1, 1>>>();
    assign_kernel<<<T_TOK / 256, 256>>>();
    gather_split_kernel<<<NROWS, 256>>>(x);

    int w1n4 = NEXP * HID * FF2 / 4;
    int w2n4 = NEXP * FF * HID / 4;
    split_w_kernel<<<(w1n4 + 255) / 256, 256>>>(w1, d_w1_hi, d_w1_lo, w1n4);
    split_w_kernel<<<(w2n4 + 255) / 256, 256>>>(w2, d_w2_hi, d_w2_lo, w2n4);

    // GEMM1: MANUAL-LDS mma variant -> check -> conditional SIMT fallback
    mma_gemm_kernel<0, 0><<<dim3(128, FF2 / 128, NEXP), 256>>>();
    check_kernel<0><<<8192, 256>>>(x, w1);
    simt_gemm_kernel<0><<<dim3(128, FF2 / 128, NEXP), 256>>>(x, w1);

    swiglu_split_kernel<<<NROWS, 256>>>();
    swiglu_refresh_kernel<<<NROWS, 256>>>();

    // GEMM2: LDMATRIX mma variant (control) -> check -> conditional SIMT fallback
    mma_gemm_kernel<1, 1><<<dim3(128, HID / 128, NEXP), 256>>>();
    check_kernel<1><<<8192, 256>>>(x, w2);
    simt_gemm_kernel<1><<<dim3(128, HID / 128, NEXP), 256>>>(nullptr, w2);

    combine_kernel<<<(T_TOK * (HID / 4)) / 256, 256>>>(out);
}